// round 7
// baseline (speedup 1.0000x reference)
#include <cuda_runtime.h>
#include <cuda_bf16.h>
#include <cuda_pipeline_primitives.h>
#include <mma.h>
#include <math.h>

// ---------------- problem constants ----------------
#define NFFT    1881
#define KPAD    1888
#define STEPSZ  941
#define ZB      109
#define NFRAMES 468
#define NBATCH  8
#define MTOT    (NBATCH*NFRAMES)
#define MPAD    3840
#define NBINS   765
#define NPAD    1536
#define TLEN    441000
#define LOG2_10 3.321928094887362f
#define KLO     20
#define KHI     71
#define KWIN    (KHI-KLO)
#define GK      16
#define NT      (KPAD/GK)
#define RS      24

// ---------------- scratch (static device memory; no allocations) ----------------
__device__ __align__(16) __nv_bfloat16 g_XFh[MTOT * KPAD];
__device__ __align__(16) __nv_bfloat16 g_XFl[MTOT * KPAD];
__device__ __align__(16) __nv_bfloat16 g_TWh[NPAD * KPAD];
__device__ __align__(16) __nv_bfloat16 g_TWl[NPAD * KPAD];
__device__ __align__(16) float g_CM[MPAD * NPAD];
__device__ __align__(16) float g_BARK[NBINS * 112];
__device__ __align__(16) float g_UEP[MTOT * 112];
__device__ __align__(16) float g_SM[NBATCH * ZB * NFRAMES];
__device__ __align__(16) float2 g_TRIG[NFFT];
__device__ __align__(16) float g_CALSW[10 * NFFT];
__device__ float g_ESC[NBINS];
__device__ float g_W[KPAD];
__device__ float g_FC[ZB], g_SU0[ZB], g_WN[ZB], g_A[ZB], g_NORMI[ZB];
__device__ float g_FMAG[10 * KWIN];
__device__ float g_FAC[1];

// ---------------- setup: window, tables, band constants, Ec-based norm_inv ----------------
__global__ void k_consts() {
    int tid = threadIdx.x;
    for (int n = tid; n < KPAD; n += blockDim.x)
        g_W[n] = (n < NFFT) ? (float)(0.5 * (1.0 - cospi(2.0 * n / 1880.0))) : 0.f;
    for (int m = tid; m < NFFT; m += blockDim.x) {
        double ph = 2.0 * (double)m / 1881.0;
        g_TRIG[m] = make_float2((float)cospi(ph), (float)sinpi(ph));
    }
    for (int i = tid; i < 10 * NFFT; i += blockDim.x) {
        int fr = i / NFFT, n = i % NFFT;
        int t = fr * STEPSZ + n;
        int p = (t * 2039) % 88200;
        float sv = sinpif((float)p * (1.0f / 44100.0f));
        float wp = 0.5f * (1.0f - cospif((float)(2 * n) * (1.0f / 1881.0f)));
        g_CALSW[i] = wp * sv;
    }
    for (int j = tid; j < NBINS; j += blockDim.x) {
        int bin = j + 3;
        float f = 22050.0f * (float)bin / 941.0f;
        float fk = f * 0.001f;
        float lgfk = log2f(fk);
        float Wdb = -2.184f * exp2f(-0.8f * lgfk)
                  + 6.5f * expf(-0.6f * (fk - 3.3f) * (fk - 3.3f))
                  - 0.001f * exp2f(3.6f * lgfk);
        g_ESC[j] = exp2f(Wdb * (LOG2_10 / 20.f)) * (1.0f / 1881.0f);
    }
    if (tid < ZB) {
        double zL = 7.0 * asinh(80.0 / 650.0);
        double ze = zL + 0.25 * tid;
        double fcd = 650.0 * sinh((ze + 0.125) / 7.0);
        float fc = (float)fcd;
        g_FC[tid] = fc;
        g_SU0[tid] = -24.0f - 230.0f / fc;
        g_WN[tid] = (float)pow(10.0, 0.4 * 0.364 * pow(fcd / 1000.0, -0.8));
        double tau = 0.008 + 2.2 / fcd;
        g_A[tid] = (float)exp(-4.0 / (187.5 * tau));
    }
    __syncthreads();
    __shared__ float srow[ZB];
    if (tid < ZB) {
        int r = tid; float s = 0.f;
        for (int c = 0; c < ZB; c++) {
            float slope = (r <= c) ? 27.0f : g_SU0[r];
            float e = fminf(0.025f * (float)(r - c) * slope, 30.0f);
            s += exp2f(e * LOG2_10);
        }
        srow[r] = s;
    }
    __syncthreads();
    if (tid < ZB) {
        int r = tid; float t = 0.f;
        for (int c = 0; c < ZB; c++) {
            float slope = (r <= c) ? 27.0f : g_SU0[r];
            float e = fminf(0.025f * (float)(r - c) * slope, 30.0f);
            float ec = exp2f(e * LOG2_10) / srow[c];
            t += exp2f(0.4f * log2f(ec));
        }
        g_NORMI[r] = exp2f(-2.5f * log2f(t));
    }
}

// ---------------- setup: bark overlap matrix (fp64, faithful) ----------------
__global__ void k_barkmat() {
    int idx = blockIdx.x * blockDim.x + threadIdx.x;
    if (idx >= NBINS * ZB) return;
    int k = idx / ZB, j = idx % ZB;
    double df = 44100.0 / 1881.0;
    int bin = k + 3;
    double blo = bin * df - df / 2.0, bhi = bin * df + df / 2.0;
    double zL = 7.0 * asinh(80.0 / 650.0);
    double felo = 650.0 * sinh((zL + 0.25 * j) / 7.0);
    double fehi = 650.0 * sinh((zL + 0.25 * (j + 1)) / 7.0);
    double ov = fmin(bhi, fehi) - fmax(blo, felo);
    ov = fmax(ov, 0.0) / df;
    g_BARK[k * 112 + j] = (float)ov;
}

// ---------------- setup: FAC calibration (peak near bin 43.5) ----------------
__global__ void k_facmag() {
    int k = blockIdx.x + KLO;
    int fr = blockIdx.y;
    int tid = threadIdx.x;
    const float* sw = &g_CALSW[fr * NFFT];
    float re = 0.f, im = 0.f;
    for (int n = tid; n < NFFT; n += 128) {
        int m = (k * n) % NFFT;
        float2 t = g_TRIG[m];
        float wx = sw[n];
        re += wx * t.x;
        im += wx * t.y;
    }
    __shared__ float sre[128], sim[128];
    sre[tid] = re; sim[tid] = im; __syncthreads();
    for (int o = 64; o > 0; o >>= 1) {
        if (tid < o) { sre[tid] += sre[tid + o]; sim[tid] += sim[tid + o]; }
        __syncthreads();
    }
    if (tid == 0) g_FMAG[fr * KWIN + blockIdx.x] = sqrtf(sre[0] * sre[0] + sim[0] * sim[0]);
}

__global__ void k_facred() {
    int w = threadIdx.x >> 5, lane = threadIdx.x & 31;
    __shared__ float fmx[10];
    if (w < 10) {
        float mx = 0.f;
        for (int k = lane; k < KWIN; k += 32) mx = fmaxf(mx, g_FMAG[w * KWIN + k]);
        for (int o = 16; o > 0; o >>= 1) mx = fmaxf(mx, __shfl_xor_sync(0xffffffff, mx, o));
        if (lane == 0) fmx[w] = mx;
    }
    __syncthreads();
    if (threadIdx.x == 0) {
        float total = 0.f;
        for (int fr = 0; fr < 10; fr++) total += fmx[fr];
        g_FAC[0] = exp2f(4.6f * LOG2_10) / (total * 0.1f);
    }
}

// ---------------- setup: transposed twiddle matrix, split bf16 hi/lo ----------------
__global__ void k_tw() {
    int col = blockIdx.x;
    float fac = g_FAC[0];
    int j = col >> 1;
    float sc = (j < NBINS) ? fac * g_ESC[j] : 0.f;
    int bin = j + 3;
    for (int n = threadIdx.x; n < KPAD; n += blockDim.x) {
        float v = 0.f;
        if (n < NFFT && j < NBINS) {
            int m = (bin * n) % NFFT;
            float2 t = g_TRIG[m];
            v = ((col & 1) ? t.y : t.x) * sc;
        }
        __nv_bfloat16 h = __float2bfloat16(v);
        float r = v - __bfloat162float(h);
        size_t o = (size_t)col * KPAD + n;
        g_TWh[o] = h;
        g_TWl[o] = __float2bfloat16(r);
    }
}

// ---------------- window + frame, split bf16 hi/lo ----------------
__global__ void k_window(const float* __restrict__ pred, const float* __restrict__ targ) {
    int fg = blockIdx.x;
    int b = fg / NFRAMES, f = fg % NFRAMES;
    const float* src = (b < 4) ? pred + (size_t)b * TLEN : targ + (size_t)(b - 4) * TLEN;
    int start = f * STEPSZ;
    for (int n = threadIdx.x; n < KPAD; n += blockDim.x) {
        float v = 0.f;
        if (n < NFFT) {
            int s = start + n;
            float xv = (s < TLEN) ? src[s] : 0.f;
            v = xv * g_W[n];
        }
        __nv_bfloat16 h = __float2bfloat16(v);
        float r = v - __bfloat162float(h);
        size_t o = (size_t)fg * KPAD + n;
        g_XFh[o] = h;
        g_XFl[o] = __float2bfloat16(r);
    }
}

// ---------------- split-bf16 tensor GEMM via wmma + async pipeline ----------------
// 128x128 block, 4 warps (64x64 warp tile), 2-stage cp.async double buffer.
// No inline asm, no function-like macros.
__global__ __launch_bounds__(128, 2) void k_gemm() {
    using namespace nvcuda;
    __shared__ __align__(16) __nv_bfloat16 sAh[2][128][RS];
    __shared__ __align__(16) __nv_bfloat16 sAl[2][128][RS];
    __shared__ __align__(16) __nv_bfloat16 sBh[2][128][RS];
    __shared__ __align__(16) __nv_bfloat16 sBl[2][128][RS];

    const int tid = threadIdx.x;
    const int w = tid >> 5;
    const int wm = w & 1;          // 2 warp-rows  -> 64 M each
    const int wn = w >> 1;         // 2 warp-cols  -> 64 N each
    const int row0 = blockIdx.y * 128, col0 = blockIdx.x * 128;

    const int lr = tid;            // loader row 0..127 (one full 32B k-slab row/thread)
    const int gr = row0 + lr;
    const size_t aoff = (size_t)((gr < MTOT) ? gr : 0) * KPAD;
    const size_t boff = (size_t)(col0 + lr) * KPAD;

    auto load_stage = [&](int st, int kt) {
        const __nv_bfloat16* pah = g_XFh + aoff + kt * GK;
        const __nv_bfloat16* pal = g_XFl + aoff + kt * GK;
        const __nv_bfloat16* pbh = g_TWh + boff + kt * GK;
        const __nv_bfloat16* pbl = g_TWl + boff + kt * GK;
        __pipeline_memcpy_async(&sAh[st][lr][0], pah, 16);
        __pipeline_memcpy_async(&sAh[st][lr][8], pah + 8, 16);
        __pipeline_memcpy_async(&sAl[st][lr][0], pal, 16);
        __pipeline_memcpy_async(&sAl[st][lr][8], pal + 8, 16);
        __pipeline_memcpy_async(&sBh[st][lr][0], pbh, 16);
        __pipeline_memcpy_async(&sBh[st][lr][8], pbh + 8, 16);
        __pipeline_memcpy_async(&sBl[st][lr][0], pbl, 16);
        __pipeline_memcpy_async(&sBl[st][lr][8], pbl + 8, 16);
        __pipeline_commit();
    };

    load_stage(0, 0);
    load_stage(1, 1);

    wmma::fragment<wmma::accumulator, 16, 16, 16, float> acc[4][4];
    for (int i = 0; i < 4; i++) {
        for (int j = 0; j < 4; j++) wmma::fill_fragment(acc[i][j], 0.f);
    }

    for (int kt = 0; kt < NT; kt++) {
        if (kt + 1 < NT) __pipeline_wait_prior(1);
        else             __pipeline_wait_prior(0);
        __syncthreads();
        const int cur = kt & 1;

        wmma::fragment<wmma::matrix_b, 16, 16, 16, __nv_bfloat16, wmma::col_major> fbh[4], fbl[4];
        for (int ni = 0; ni < 4; ni++) {
            wmma::load_matrix_sync(fbh[ni], &sBh[cur][wn * 64 + ni * 16][0], RS);
            wmma::load_matrix_sync(fbl[ni], &sBl[cur][wn * 64 + ni * 16][0], RS);
        }
        for (int mi = 0; mi < 4; mi++) {
            wmma::fragment<wmma::matrix_a, 16, 16, 16, __nv_bfloat16, wmma::row_major> fah, fal;
            wmma::load_matrix_sync(fah, &sAh[cur][wm * 64 + mi * 16][0], RS);
            wmma::load_matrix_sync(fal, &sAl[cur][wm * 64 + mi * 16][0], RS);
            for (int ni = 0; ni < 4; ni++) {
                wmma::mma_sync(acc[mi][ni], fah, fbh[ni], acc[mi][ni]);
                wmma::mma_sync(acc[mi][ni], fah, fbl[ni], acc[mi][ni]);
                wmma::mma_sync(acc[mi][ni], fal, fbh[ni], acc[mi][ni]);
            }
        }
        __syncthreads();
        if (kt + 2 < NT) load_stage(cur, kt + 2);
    }

    for (int mi = 0; mi < 4; mi++) {
        for (int ni = 0; ni < 4; ni++) {
            size_t r = (size_t)(row0 + wm * 64 + mi * 16);
            size_t c = (size_t)(col0 + wn * 64 + ni * 16);
            wmma::store_matrix_sync(&g_CM[r * NPAD + c], acc[mi][ni], NPAD, wmma::mem_row_major);
        }
    }
}

// ---------------- |X|^2 -> bark energies (+ internal noise), 8 frames/block ----------------
__global__ void k_bark() {
    int fb = blockIdx.x;
    int tid = threadIdx.x;
    __shared__ float P[8][768];
    for (int i = 0; i < 8; i++) {
        int fg = fb * 8 + i;
        const float2* crow = (const float2*)&g_CM[(size_t)fg * NPAD];
        for (int j = tid; j < NBINS; j += 128) {
            float2 c = crow[j];
            P[i][j] = c.x * c.x + c.y * c.y;
        }
    }
    __syncthreads();
    if (tid < ZB) {
        float acc[8] = {0, 0, 0, 0, 0, 0, 0, 0};
        for (int j = 0; j < NBINS; j++) {
            float bv = g_BARK[j * 112 + tid];
            for (int i = 0; i < 8; i++) acc[i] += P[i][j] * bv;
        }
        float wn = g_WN[tid];
        for (int i = 0; i < 8; i++)
            g_UEP[(size_t)(fb * 8 + i) * 112 + tid] = fmaxf(acc[i], 1e-12f) + wn;
    }
}

// ---------------- frequency smearing (faithful to reference broadcasts) ----------------
__global__ void k_smear() {
    int fg = blockIdx.x;
    int tid = threadIdx.x;
    __shared__ float m2[ZB], Su[ZB], icol[ZB];
    if (tid < ZB) {
        float lg = log2f(g_UEP[(size_t)fg * 112 + tid]);
        float L = 3.0102999566f * lg;
        m2[tid] = fminf(0.30102999566f * lg, 30.0f);
        Su[tid] = g_SU0[tid] + 0.2f * L;
    }
    __syncthreads();
    if (tid < ZB) {
        int c = tid;
        float colsum = 0.f;
        for (int r = 0; r < ZB; r++) {
            float slope = (r <= c) ? 27.0f : Su[r];
            float e1 = 0.025f * (float)(r - c) * slope;
            float m = fminf(e1, 30.0f) + m2[r];
            colsum += exp2f(m * LOG2_10);
        }
        icol[c] = exp2f(-0.4f * log2f(colsum));
    }
    __syncthreads();
    if (tid < ZB) {
        int c = tid;
        float acc = 0.f;
        for (int r = 0; r < ZB; r++) {
            float slope = (r <= c) ? 27.0f : Su[r];
            float e1 = 0.025f * (float)(r - c) * slope;
            float m = fminf(e1, 30.0f) + m2[r];
            acc += exp2f(0.4f * LOG2_10 * m) * icol[r];
        }
        float E2 = exp2f(2.5f * log2f(acc)) * g_NORMI[c];
        int b = fg / NFRAMES, f = fg % NFRAMES;
        g_SM[((size_t)b * ZB + c) * NFRAMES + f] = E2;
    }
}

// ---------------- per-band IIR + max ----------------
__global__ void k_iir(float* __restrict__ out) {
    int idx = blockIdx.x * blockDim.x + threadIdx.x;
    if (idx >= NBATCH * ZB) return;
    int z = idx % ZB;
    float a = g_A[z], b0 = 1.f - a;
    const float* row = &g_SM[(size_t)idx * NFRAMES];
    float* orow = &out[(size_t)idx * NFRAMES];
    float ef = 0.f;
    for (int t = 0; t < NFRAMES; t++) {
        float u = row[t];
        float xin = (t == 0) ? 0.f : u;
        ef = fmaf(a, ef, b0 * xin);
        orow[t] = fmaxf(ef, u);
    }
}

// ---------------- launch ----------------
extern "C" void kernel_launch(void* const* d_in, const int* in_sizes, int n_in,
                              void* d_out, int out_size) {
    const float* pred = (const float*)d_in[0];
    const float* targ = (const float*)d_in[1];
    float* out = (float*)d_out;

    k_consts<<<1, 256>>>();
    k_barkmat<<<(NBINS * ZB + 255) / 256, 256>>>();
    k_facmag<<<dim3(KWIN, 10), 128>>>();
    k_facred<<<1, 320>>>();
    k_tw<<<NPAD, 256>>>();
    k_window<<<MTOT, 256>>>(pred, targ);
    k_gemm<<<dim3(NPAD / 128, MPAD / 128), 128>>>();
    k_bark<<<NFRAMES, 128>>>();
    k_smear<<<MTOT, 128>>>();
    k_iir<<<(NBATCH * ZB + 127) / 128, 128>>>(out);
}

// round 8
// speedup vs baseline: 1.0805x; 1.0805x over previous
#include <cuda_runtime.h>
#include <cuda_bf16.h>
#include <cuda_pipeline_primitives.h>
#include <mma.h>
#include <math.h>

// ---------------- problem constants ----------------
#define NFFT    1881
#define KPAD    1888
#define STEPSZ  941
#define ZB      109
#define NFRAMES 468
#define NBATCH  8
#define MTOT    (NBATCH*NFRAMES)
#define MPAD    3840
#define NBINS   765
#define NPAD    1536
#define TLEN    441000
#define LOG2_10 3.321928094887362f
#define KLO     20
#define KHI     71
#define KWIN    (KHI-KLO)
#define GK      16
#define NT      (KPAD/GK)
#define RS      24

// ---------------- scratch (static device memory; no allocations) ----------------
__device__ __align__(16) __nv_bfloat16 g_XFh[MTOT * KPAD];
__device__ __align__(16) __nv_bfloat16 g_XFl[MTOT * KPAD];
__device__ __align__(16) __nv_bfloat16 g_TWh[NPAD * KPAD];
__device__ __align__(16) __nv_bfloat16 g_TWl[NPAD * KPAD];
__device__ __align__(16) float g_CM[MPAD * NPAD];
__device__ __align__(16) float g_BARK[NBINS * 112];
__device__ __align__(16) float g_UEP[MTOT * 112];
__device__ __align__(16) float g_SM[NBATCH * ZB * NFRAMES];
__device__ __align__(16) float2 g_TRIG[NFFT];
__device__ __align__(16) float g_CALSW[10 * NFFT];
__device__ float g_ESC[NBINS];
__device__ float g_W[KPAD];
__device__ float g_FC[ZB], g_SU0[ZB], g_WN[ZB], g_A[ZB], g_NORMI[ZB];
__device__ float g_FMAG[10 * KWIN];
__device__ float g_FAC[1];

// ---------------- setup: window, tables, band constants, Ec-based norm_inv ----------------
__global__ void k_consts() {
    int tid = threadIdx.x;
    for (int n = tid; n < KPAD; n += blockDim.x)
        g_W[n] = (n < NFFT) ? (float)(0.5 * (1.0 - cospi(2.0 * n / 1880.0))) : 0.f;
    for (int m = tid; m < NFFT; m += blockDim.x) {
        double ph = 2.0 * (double)m / 1881.0;
        g_TRIG[m] = make_float2((float)cospi(ph), (float)sinpi(ph));
    }
    for (int i = tid; i < 10 * NFFT; i += blockDim.x) {
        int fr = i / NFFT, n = i % NFFT;
        int t = fr * STEPSZ + n;
        int p = (t * 2039) % 88200;
        float sv = sinpif((float)p * (1.0f / 44100.0f));
        float wp = 0.5f * (1.0f - cospif((float)(2 * n) * (1.0f / 1881.0f)));
        g_CALSW[i] = wp * sv;
    }
    for (int j = tid; j < NBINS; j += blockDim.x) {
        int bin = j + 3;
        float f = 22050.0f * (float)bin / 941.0f;
        float fk = f * 0.001f;
        float lgfk = log2f(fk);
        float Wdb = -2.184f * exp2f(-0.8f * lgfk)
                  + 6.5f * expf(-0.6f * (fk - 3.3f) * (fk - 3.3f))
                  - 0.001f * exp2f(3.6f * lgfk);
        g_ESC[j] = exp2f(Wdb * (LOG2_10 / 20.f)) * (1.0f / 1881.0f);
    }
    if (tid < ZB) {
        double zL = 7.0 * asinh(80.0 / 650.0);
        double ze = zL + 0.25 * tid;
        double fcd = 650.0 * sinh((ze + 0.125) / 7.0);
        float fc = (float)fcd;
        g_FC[tid] = fc;
        g_SU0[tid] = -24.0f - 230.0f / fc;
        g_WN[tid] = (float)pow(10.0, 0.4 * 0.364 * pow(fcd / 1000.0, -0.8));
        double tau = 0.008 + 2.2 / fcd;
        g_A[tid] = (float)exp(-4.0 / (187.5 * tau));
    }
    __syncthreads();
    __shared__ float srow[ZB];
    if (tid < ZB) {
        int r = tid; float s = 0.f;
        for (int c = 0; c < ZB; c++) {
            float slope = (r <= c) ? 27.0f : g_SU0[r];
            float e = fminf(0.025f * (float)(r - c) * slope, 30.0f);
            s += exp2f(e * LOG2_10);
        }
        srow[r] = s;
    }
    __syncthreads();
    if (tid < ZB) {
        int r = tid; float t = 0.f;
        for (int c = 0; c < ZB; c++) {
            float slope = (r <= c) ? 27.0f : g_SU0[r];
            float e = fminf(0.025f * (float)(r - c) * slope, 30.0f);
            float ec = exp2f(e * LOG2_10) / srow[c];
            t += exp2f(0.4f * log2f(ec));
        }
        g_NORMI[r] = exp2f(-2.5f * log2f(t));
    }
}

// ---------------- setup: bark overlap matrix (fp64, faithful) ----------------
__global__ void k_barkmat() {
    int idx = blockIdx.x * blockDim.x + threadIdx.x;
    if (idx >= NBINS * ZB) return;
    int k = idx / ZB, j = idx % ZB;
    double df = 44100.0 / 1881.0;
    int bin = k + 3;
    double blo = bin * df - df / 2.0, bhi = bin * df + df / 2.0;
    double zL = 7.0 * asinh(80.0 / 650.0);
    double felo = 650.0 * sinh((zL + 0.25 * j) / 7.0);
    double fehi = 650.0 * sinh((zL + 0.25 * (j + 1)) / 7.0);
    double ov = fmin(bhi, fehi) - fmax(blo, felo);
    ov = fmax(ov, 0.0) / df;
    g_BARK[k * 112 + j] = (float)ov;
}

// ---------------- setup: FAC calibration (peak near bin 43.5) ----------------
__global__ void k_facmag() {
    int k = blockIdx.x + KLO;
    int fr = blockIdx.y;
    int tid = threadIdx.x;
    const float* sw = &g_CALSW[fr * NFFT];
    float re = 0.f, im = 0.f;
    for (int n = tid; n < NFFT; n += 128) {
        int m = (k * n) % NFFT;
        float2 t = g_TRIG[m];
        float wx = sw[n];
        re += wx * t.x;
        im += wx * t.y;
    }
    __shared__ float sre[128], sim[128];
    sre[tid] = re; sim[tid] = im; __syncthreads();
    for (int o = 64; o > 0; o >>= 1) {
        if (tid < o) { sre[tid] += sre[tid + o]; sim[tid] += sim[tid + o]; }
        __syncthreads();
    }
    if (tid == 0) g_FMAG[fr * KWIN + blockIdx.x] = sqrtf(sre[0] * sre[0] + sim[0] * sim[0]);
}

__global__ void k_facred() {
    int w = threadIdx.x >> 5, lane = threadIdx.x & 31;
    __shared__ float fmx[10];
    if (w < 10) {
        float mx = 0.f;
        for (int k = lane; k < KWIN; k += 32) mx = fmaxf(mx, g_FMAG[w * KWIN + k]);
        for (int o = 16; o > 0; o >>= 1) mx = fmaxf(mx, __shfl_xor_sync(0xffffffff, mx, o));
        if (lane == 0) fmx[w] = mx;
    }
    __syncthreads();
    if (threadIdx.x == 0) {
        float total = 0.f;
        for (int fr = 0; fr < 10; fr++) total += fmx[fr];
        g_FAC[0] = exp2f(4.6f * LOG2_10) / (total * 0.1f);
    }
}

// ---------------- setup: transposed twiddle matrix, split bf16 hi/lo ----------------
__global__ void k_tw() {
    int col = blockIdx.x;
    float fac = g_FAC[0];
    int j = col >> 1;
    float sc = (j < NBINS) ? fac * g_ESC[j] : 0.f;
    int bin = j + 3;
    for (int n = threadIdx.x; n < KPAD; n += blockDim.x) {
        float v = 0.f;
        if (n < NFFT && j < NBINS) {
            int m = (bin * n) % NFFT;
            float2 t = g_TRIG[m];
            v = ((col & 1) ? t.y : t.x) * sc;
        }
        __nv_bfloat16 h = __float2bfloat16(v);
        float r = v - __bfloat162float(h);
        size_t o = (size_t)col * KPAD + n;
        g_TWh[o] = h;
        g_TWl[o] = __float2bfloat16(r);
    }
}

// ---------------- window + frame, split bf16 hi/lo ----------------
__global__ void k_window(const float* __restrict__ pred, const float* __restrict__ targ) {
    int fg = blockIdx.x;
    int b = fg / NFRAMES, f = fg % NFRAMES;
    const float* src = (b < 4) ? pred + (size_t)b * TLEN : targ + (size_t)(b - 4) * TLEN;
    int start = f * STEPSZ;
    for (int n = threadIdx.x; n < KPAD; n += blockDim.x) {
        float v = 0.f;
        if (n < NFFT) {
            int s = start + n;
            float xv = (s < TLEN) ? src[s] : 0.f;
            v = xv * g_W[n];
        }
        __nv_bfloat16 h = __float2bfloat16(v);
        float r = v - __bfloat162float(h);
        size_t o = (size_t)fg * KPAD + n;
        g_XFh[o] = h;
        g_XFl[o] = __float2bfloat16(r);
    }
}

// ---------------- split-bf16 tensor GEMM: R5 shape (8 warps, 64x32 warp tile)
// + 2-stage cp.async double buffer. No inline asm, no function-like macros.
__global__ __launch_bounds__(256) void k_gemm() {
    using namespace nvcuda;
    __shared__ __align__(16) __nv_bfloat16 sAh[2][128][RS];
    __shared__ __align__(16) __nv_bfloat16 sAl[2][128][RS];
    __shared__ __align__(16) __nv_bfloat16 sBh[2][128][RS];
    __shared__ __align__(16) __nv_bfloat16 sBl[2][128][RS];

    const int tid = threadIdx.x;
    const int w = tid >> 5;
    const int wm = w & 1;          // 2 warp-rows -> 64 M each
    const int wn = w >> 1;         // 4 warp-cols -> 32 N each
    const int row0 = blockIdx.y * 128, col0 = blockIdx.x * 128;

    const int lr = tid >> 1;            // loader row 0..127
    const int lh = (tid & 1) * 8;       // k-half 0/8
    const int gr = row0 + lr;
    const size_t aoff = (size_t)((gr < MTOT) ? gr : 0) * KPAD + lh;
    const size_t boff = (size_t)(col0 + lr) * KPAD + lh;

    auto load_stage = [&](int st, int kt) {
        size_t kk = (size_t)kt * GK;
        __pipeline_memcpy_async(&sAh[st][lr][lh], g_XFh + aoff + kk, 16);
        __pipeline_memcpy_async(&sAl[st][lr][lh], g_XFl + aoff + kk, 16);
        __pipeline_memcpy_async(&sBh[st][lr][lh], g_TWh + boff + kk, 16);
        __pipeline_memcpy_async(&sBl[st][lr][lh], g_TWl + boff + kk, 16);
        __pipeline_commit();
    };

    load_stage(0, 0);
    load_stage(1, 1);

    wmma::fragment<wmma::accumulator, 16, 16, 16, float> acc[4][2];
    for (int i = 0; i < 4; i++) {
        for (int j = 0; j < 2; j++) wmma::fill_fragment(acc[i][j], 0.f);
    }

    for (int kt = 0; kt < NT; kt++) {
        if (kt + 1 < NT) __pipeline_wait_prior(1);
        else             __pipeline_wait_prior(0);
        __syncthreads();
        const int cur = kt & 1;

        wmma::fragment<wmma::matrix_b, 16, 16, 16, __nv_bfloat16, wmma::col_major> fbh[2], fbl[2];
        for (int ni = 0; ni < 2; ni++) {
            wmma::load_matrix_sync(fbh[ni], &sBh[cur][wn * 32 + ni * 16][0], RS);
            wmma::load_matrix_sync(fbl[ni], &sBl[cur][wn * 32 + ni * 16][0], RS);
        }
        for (int mi = 0; mi < 4; mi++) {
            wmma::fragment<wmma::matrix_a, 16, 16, 16, __nv_bfloat16, wmma::row_major> fah, fal;
            wmma::load_matrix_sync(fah, &sAh[cur][wm * 64 + mi * 16][0], RS);
            wmma::load_matrix_sync(fal, &sAl[cur][wm * 64 + mi * 16][0], RS);
            for (int ni = 0; ni < 2; ni++) {
                wmma::mma_sync(acc[mi][ni], fah, fbh[ni], acc[mi][ni]);
                wmma::mma_sync(acc[mi][ni], fah, fbl[ni], acc[mi][ni]);
                wmma::mma_sync(acc[mi][ni], fal, fbh[ni], acc[mi][ni]);
            }
        }
        __syncthreads();
        if (kt + 2 < NT) load_stage(cur, kt + 2);
    }

    for (int mi = 0; mi < 4; mi++) {
        for (int ni = 0; ni < 2; ni++) {
            size_t r = (size_t)(row0 + wm * 64 + mi * 16);
            size_t c = (size_t)(col0 + wn * 32 + ni * 16);
            wmma::store_matrix_sync(&g_CM[r * NPAD + c], acc[mi][ni], NPAD, wmma::mem_row_major);
        }
    }
}

// ---------------- |X|^2 -> bark energies (+ internal noise), 8 frames/block ----------------
__global__ void k_bark() {
    int fb = blockIdx.x;
    int tid = threadIdx.x;
    __shared__ float P[8][768];
    for (int i = 0; i < 8; i++) {
        int fg = fb * 8 + i;
        const float2* crow = (const float2*)&g_CM[(size_t)fg * NPAD];
        for (int j = tid; j < NBINS; j += 128) {
            float2 c = crow[j];
            P[i][j] = c.x * c.x + c.y * c.y;
        }
    }
    __syncthreads();
    if (tid < ZB) {
        float acc[8] = {0, 0, 0, 0, 0, 0, 0, 0};
        for (int j = 0; j < NBINS; j++) {
            float bv = g_BARK[j * 112 + tid];
            for (int i = 0; i < 8; i++) acc[i] += P[i][j] * bv;
        }
        float wn = g_WN[tid];
        for (int i = 0; i < 8; i++)
            g_UEP[(size_t)(fb * 8 + i) * 112 + tid] = fmaxf(acc[i], 1e-12f) + wn;
    }
}

// ---------------- frequency smearing (faithful to reference broadcasts) ----------------
__global__ void k_smear() {
    int fg = blockIdx.x;
    int tid = threadIdx.x;
    __shared__ float m2[ZB], Su[ZB], icol[ZB];
    if (tid < ZB) {
        float lg = log2f(g_UEP[(size_t)fg * 112 + tid]);
        float L = 3.0102999566f * lg;
        m2[tid] = fminf(0.30102999566f * lg, 30.0f);
        Su[tid] = g_SU0[tid] + 0.2f * L;
    }
    __syncthreads();
    if (tid < ZB) {
        int c = tid;
        float colsum = 0.f;
        for (int r = 0; r < ZB; r++) {
            float slope = (r <= c) ? 27.0f : Su[r];
            float e1 = 0.025f * (float)(r - c) * slope;
            float m = fminf(e1, 30.0f) + m2[r];
            colsum += exp2f(m * LOG2_10);
        }
        icol[c] = exp2f(-0.4f * log2f(colsum));
    }
    __syncthreads();
    if (tid < ZB) {
        int c = tid;
        float acc = 0.f;
        for (int r = 0; r < ZB; r++) {
            float slope = (r <= c) ? 27.0f : Su[r];
            float e1 = 0.025f * (float)(r - c) * slope;
            float m = fminf(e1, 30.0f) + m2[r];
            acc += exp2f(0.4f * LOG2_10 * m) * icol[r];
        }
        float E2 = exp2f(2.5f * log2f(acc)) * g_NORMI[c];
        int b = fg / NFRAMES, f = fg % NFRAMES;
        g_SM[((size_t)b * ZB + c) * NFRAMES + f] = E2;
    }
}

// ---------------- per-band IIR + max ----------------
__global__ void k_iir(float* __restrict__ out) {
    int idx = blockIdx.x * blockDim.x + threadIdx.x;
    if (idx >= NBATCH * ZB) return;
    int z = idx % ZB;
    float a = g_A[z], b0 = 1.f - a;
    const float* row = &g_SM[(size_t)idx * NFRAMES];
    float* orow = &out[(size_t)idx * NFRAMES];
    float ef = 0.f;
    for (int t = 0; t < NFRAMES; t++) {
        float u = row[t];
        float xin = (t == 0) ? 0.f : u;
        ef = fmaf(a, ef, b0 * xin);
        orow[t] = fmaxf(ef, u);
    }
}

// ---------------- launch ----------------
extern "C" void kernel_launch(void* const* d_in, const int* in_sizes, int n_in,
                              void* d_out, int out_size) {
    const float* pred = (const float*)d_in[0];
    const float* targ = (const float*)d_in[1];
    float* out = (float*)d_out;

    k_consts<<<1, 256>>>();
    k_barkmat<<<(NBINS * ZB + 255) / 256, 256>>>();
    k_facmag<<<dim3(KWIN, 10), 128>>>();
    k_facred<<<1, 320>>>();
    k_tw<<<NPAD, 256>>>();
    k_window<<<MTOT, 256>>>(pred, targ);
    k_gemm<<<dim3(NPAD / 128, MPAD / 128), 256>>>();
    k_bark<<<NFRAMES, 128>>>();
    k_smear<<<MTOT, 128>>>();
    k_iir<<<(NBATCH * ZB + 127) / 128, 128>>>(out);
}

// round 9
// speedup vs baseline: 1.5903x; 1.4719x over previous
#include <cuda_runtime.h>
#include <cuda_bf16.h>
#include <mma.h>
#include <math.h>

// ---------------- problem constants ----------------
#define NFFT    1881
#define STEPSZ  941
#define ZB      109
#define NFRAMES 468
#define NBATCH  8
#define MTOT    (NBATCH*NFRAMES)
#define MPAD    3840
#define NBINS   765
#define TLEN    441000
#define LOG2_10 3.321928094887362f
#define KLO     20
#define KHI     71
#define KWIN    (KHI-KLO)
#define RS      24
// CT factorization: 1881 = 9 x 209
#define N2CNT   209
#define KP2     432            // 2*209 = 418 padded to 432 (27 x 16)
#define NT2     (KP2/16)       // 27
#define NCLS    9
#define NPC     192            // per-class N: 85 bins x2 padded to 192
#define ROWW    (NCLS*NPC)     // 1728 floats per CM row

// ---------------- scratch (static device memory; no allocations) ----------------
__device__ __align__(16) __nv_bfloat16 g_Ah[(size_t)NCLS * MPAD * KP2];
__device__ __align__(16) __nv_bfloat16 g_Al[(size_t)NCLS * MPAD * KP2];
__device__ __align__(16) __nv_bfloat16 g_Bh[NCLS * NPC * KP2];
__device__ __align__(16) __nv_bfloat16 g_Bl[NCLS * NPC * KP2];
__device__ __align__(16) float g_CM[(size_t)MPAD * ROWW];
__device__ __align__(16) float g_BARK[NBINS * 112];
__device__ __align__(16) float g_UEP[MTOT * 112];
__device__ __align__(16) float g_SM[NBATCH * ZB * NFRAMES];
__device__ __align__(16) float2 g_TRIG[NFFT];
__device__ __align__(16) float g_CALSW[10 * NFFT];
__device__ float g_ESC[NBINS];
__device__ float g_W[NFFT];
__device__ float g_FC[ZB], g_SU0[ZB], g_WN[ZB], g_A[ZB], g_NORMI[ZB];
__device__ float g_FMAG[10 * KWIN];
__device__ float g_FAC[1];

// ---------------- setup: window, tables, band constants, Ec-based norm_inv ----------------
__global__ void k_consts() {
    int tid = threadIdx.x;
    for (int n = tid; n < NFFT; n += blockDim.x)
        g_W[n] = (float)(0.5 * (1.0 - cospi(2.0 * n / 1880.0)));
    for (int m = tid; m < NFFT; m += blockDim.x) {
        double ph = 2.0 * (double)m / 1881.0;
        g_TRIG[m] = make_float2((float)cospi(ph), (float)sinpi(ph));
    }
    for (int i = tid; i < 10 * NFFT; i += blockDim.x) {
        int fr = i / NFFT, n = i % NFFT;
        int t = fr * STEPSZ + n;
        int p = (t * 2039) % 88200;
        float sv = sinpif((float)p * (1.0f / 44100.0f));
        float wp = 0.5f * (1.0f - cospif((float)(2 * n) * (1.0f / 1881.0f)));
        g_CALSW[i] = wp * sv;
    }
    for (int j = tid; j < NBINS; j += blockDim.x) {
        int bin = j + 3;
        float f = 22050.0f * (float)bin / 941.0f;
        float fk = f * 0.001f;
        float lgfk = log2f(fk);
        float Wdb = -2.184f * exp2f(-0.8f * lgfk)
                  + 6.5f * expf(-0.6f * (fk - 3.3f) * (fk - 3.3f))
                  - 0.001f * exp2f(3.6f * lgfk);
        g_ESC[j] = exp2f(Wdb * (LOG2_10 / 20.f)) * (1.0f / 1881.0f);
    }
    if (tid < ZB) {
        double zL = 7.0 * asinh(80.0 / 650.0);
        double ze = zL + 0.25 * tid;
        double fcd = 650.0 * sinh((ze + 0.125) / 7.0);
        float fc = (float)fcd;
        g_FC[tid] = fc;
        g_SU0[tid] = -24.0f - 230.0f / fc;
        g_WN[tid] = (float)pow(10.0, 0.4 * 0.364 * pow(fcd / 1000.0, -0.8));
        double tau = 0.008 + 2.2 / fcd;
        g_A[tid] = (float)exp(-4.0 / (187.5 * tau));
    }
    __syncthreads();
    __shared__ float srow[ZB];
    if (tid < ZB) {
        int r = tid; float s = 0.f;
        for (int c = 0; c < ZB; c++) {
            float slope = (r <= c) ? 27.0f : g_SU0[r];
            float e = fminf(0.025f * (float)(r - c) * slope, 30.0f);
            s += exp2f(e * LOG2_10);
        }
        srow[r] = s;
    }
    __syncthreads();
    if (tid < ZB) {
        int r = tid; float t = 0.f;
        for (int c = 0; c < ZB; c++) {
            float slope = (r <= c) ? 27.0f : g_SU0[r];
            float e = fminf(0.025f * (float)(r - c) * slope, 30.0f);
            float ec = exp2f(e * LOG2_10) / srow[c];
            t += exp2f(0.4f * log2f(ec));
        }
        g_NORMI[r] = exp2f(-2.5f * log2f(t));
    }
}

// ---------------- setup: bark overlap matrix (fp64, faithful) ----------------
__global__ void k_barkmat() {
    int idx = blockIdx.x * blockDim.x + threadIdx.x;
    if (idx >= NBINS * ZB) return;
    int k = idx / ZB, j = idx % ZB;
    double df = 44100.0 / 1881.0;
    int bin = k + 3;
    double blo = bin * df - df / 2.0, bhi = bin * df + df / 2.0;
    double zL = 7.0 * asinh(80.0 / 650.0);
    double felo = 650.0 * sinh((zL + 0.25 * j) / 7.0);
    double fehi = 650.0 * sinh((zL + 0.25 * (j + 1)) / 7.0);
    double ov = fmin(bhi, fehi) - fmax(blo, felo);
    ov = fmax(ov, 0.0) / df;
    g_BARK[k * 112 + j] = (float)ov;
}

// ---------------- setup: FAC calibration (peak near bin 43.5) ----------------
__global__ void k_facmag() {
    int k = blockIdx.x + KLO;
    int fr = blockIdx.y;
    int tid = threadIdx.x;
    const float* sw = &g_CALSW[fr * NFFT];
    float re = 0.f, im = 0.f;
    for (int n = tid; n < NFFT; n += 128) {
        int m = (k * n) % NFFT;
        float2 t = g_TRIG[m];
        float wx = sw[n];
        re += wx * t.x;
        im += wx * t.y;
    }
    __shared__ float sre[128], sim[128];
    sre[tid] = re; sim[tid] = im; __syncthreads();
    for (int o = 64; o > 0; o >>= 1) {
        if (tid < o) { sre[tid] += sre[tid + o]; sim[tid] += sim[tid + o]; }
        __syncthreads();
    }
    if (tid == 0) g_FMAG[fr * KWIN + blockIdx.x] = sqrtf(sre[0] * sre[0] + sim[0] * sim[0]);
}

__global__ void k_facred() {
    int w = threadIdx.x >> 5, lane = threadIdx.x & 31;
    __shared__ float fmx[10];
    if (w < 10) {
        float mx = 0.f;
        for (int k = lane; k < KWIN; k += 32) mx = fmaxf(mx, g_FMAG[w * KWIN + k]);
        for (int o = 16; o > 0; o >>= 1) mx = fmaxf(mx, __shfl_xor_sync(0xffffffff, mx, o));
        if (lane == 0) fmx[w] = mx;
    }
    __syncthreads();
    if (threadIdx.x == 0) {
        float total = 0.f;
        for (int fr = 0; fr < 10; fr++) total += fmx[fr];
        g_FAC[0] = exp2f(4.6f * LOG2_10) / (total * 0.1f);
    }
}

// ---------------- setup: per-class twiddle matrices B (split bf16 hi/lo) ----------------
// class c, bin k = k0(c)+9p; B[col even]=re-coeffs {cos,sin}, B[col odd]=im-coeffs {-sin,cos}
__global__ void k_tw2() {
    int gid = blockIdx.x;           // 0 .. 9*192-1
    int c = gid / NPC, col = gid - c * NPC;
    float fac = g_FAC[0];
    int p = col >> 1;
    int k0 = (c >= 3) ? c : c + 9;
    int k = k0 + 9 * p;
    bool valid = (p < 85);
    float sc = valid ? fac * g_ESC[k - 3] : 0.f;
    for (int q = threadIdx.x; q < KP2; q += 128) {
        float v = 0.f;
        if (valid && q < 2 * N2CNT) {
            int n2 = q >> 1;
            float2 t = g_TRIG[(k * n2) % NFFT];
            if ((col & 1) == 0) v = (q & 1) ? t.y : t.x;
            else                v = (q & 1) ? t.x : -t.y;
            v *= sc;
        }
        __nv_bfloat16 h = __float2bfloat16(v);
        float r = v - __bfloat162float(h);
        size_t o = ((size_t)c * NPC + col) * KP2 + q;
        g_Bh[o] = h;
        g_Bl[o] = __float2bfloat16(r);
    }
}

// ---------------- stage 1: window + 9-point fold -> A (split bf16 hi/lo) ----------------
__global__ void k_fold(const float* __restrict__ pred, const float* __restrict__ targ) {
    __shared__ float xw[NFFT];
    int fg = blockIdx.x;            // 0..3743
    int tid = threadIdx.x;          // 256
    int b = fg / NFRAMES, f = fg % NFRAMES;
    const float* src = (b < 4) ? pred + (size_t)b * TLEN : targ + (size_t)(b - 4) * TLEN;
    int start = f * STEPSZ;
    for (int n = tid; n < NFFT; n += 256) {
        int s = start + n;
        xw[n] = ((s < TLEN) ? src[s] : 0.f) * g_W[n];
    }
    __syncthreads();
    for (int idx = tid; idx < NFFT; idx += 256) {
        int c = idx / N2CNT;
        int n2 = idx - c * N2CNT;
        float yr = 0.f, yi = 0.f;
        for (int n1 = 0; n1 < 9; n1++) {
            int m = ((c * n1) % 9) * N2CNT;     // (209*c*n1) mod 1881
            float2 t = g_TRIG[m];
            float xv = xw[n2 + N2CNT * n1];
            yr = fmaf(xv, t.x, yr);
            yi = fmaf(-xv, t.y, yi);
        }
        size_t base = ((size_t)c * MPAD + fg) * KP2 + 2 * n2;
        __nv_bfloat16 hr = __float2bfloat16(yr);
        __nv_bfloat16 hiq = __float2bfloat16(yi);
        g_Ah[base] = hr;
        g_Ah[base + 1] = hiq;
        g_Al[base] = __float2bfloat16(yr - __bfloat162float(hr));
        g_Al[base + 1] = __float2bfloat16(yi - __bfloat162float(hiq));
    }
    // zero K padding 418..431
    if (tid < KP2 - 2 * N2CNT) {
        __nv_bfloat16 z = __float2bfloat16(0.f);
        for (int c = 0; c < NCLS; c++) {
            size_t base = ((size_t)c * MPAD + fg) * KP2 + 2 * N2CNT + tid;
            g_Ah[base] = z;
            g_Al[base] = z;
        }
    }
}

// ---------------- stage 2: split-bf16 tensor GEMM per class (R5 sync structure) ----------------
// block 128M x 192N, 8 warps (warp tile 64x48, mi4 x ni3), K=432 in 27 steps.
__global__ __launch_bounds__(256) void k_gemm2() {
    using namespace nvcuda;
    __shared__ __align__(16) __nv_bfloat16 sAh[128][RS];
    __shared__ __align__(16) __nv_bfloat16 sAl[128][RS];
    __shared__ __align__(16) __nv_bfloat16 sBh[NPC][RS];
    __shared__ __align__(16) __nv_bfloat16 sBl[NPC][RS];

    const int tid = threadIdx.x;
    const int w = tid >> 5;
    const int wm = w & 1;           // 2 warp-rows -> 64 M each
    const int wn = w >> 1;          // 4 warp-cols -> 48 N each
    const int cls = blockIdx.z;
    const int row0 = blockIdx.y * 128;

    const int lr = tid >> 1;             // A loader row 0..127
    const int lh = (tid & 1) * 8;        // k-half 0/8
    const size_t aoff = ((size_t)cls * MPAD + row0 + lr) * KP2 + lh;
    const size_t boff0 = ((size_t)cls * NPC + lr) * KP2 + lh;         // B rows 0..127
    const bool has2 = (tid < 128);
    const int lr1 = 128 + (tid >> 1);    // B rows 128..191 (tid<128)
    const size_t boff1 = ((size_t)cls * NPC + lr1) * KP2 + lh;

    uint4 rah = *(const uint4*)(g_Ah + aoff);
    uint4 ral = *(const uint4*)(g_Al + aoff);
    uint4 rbh0 = *(const uint4*)(g_Bh + boff0);
    uint4 rbl0 = *(const uint4*)(g_Bl + boff0);
    uint4 rbh1 = has2 ? *(const uint4*)(g_Bh + boff1) : make_uint4(0, 0, 0, 0);
    uint4 rbl1 = has2 ? *(const uint4*)(g_Bl + boff1) : make_uint4(0, 0, 0, 0);

    wmma::fragment<wmma::accumulator, 16, 16, 16, float> acc[4][3];
    for (int i = 0; i < 4; i++) {
        for (int j = 0; j < 3; j++) wmma::fill_fragment(acc[i][j], 0.f);
    }

    for (int kt = 0; kt < NT2; kt++) {
        __syncthreads();
        *(uint4*)(&sAh[lr][lh]) = rah;
        *(uint4*)(&sAl[lr][lh]) = ral;
        *(uint4*)(&sBh[lr][lh]) = rbh0;
        *(uint4*)(&sBl[lr][lh]) = rbl0;
        if (has2) {
            *(uint4*)(&sBh[lr1][lh]) = rbh1;
            *(uint4*)(&sBl[lr1][lh]) = rbl1;
        }
        __syncthreads();
        if (kt + 1 < NT2) {
            size_t kk = (size_t)(kt + 1) * 16;
            rah = *(const uint4*)(g_Ah + aoff + kk);
            ral = *(const uint4*)(g_Al + aoff + kk);
            rbh0 = *(const uint4*)(g_Bh + boff0 + kk);
            rbl0 = *(const uint4*)(g_Bl + boff0 + kk);
            if (has2) {
                rbh1 = *(const uint4*)(g_Bh + boff1 + kk);
                rbl1 = *(const uint4*)(g_Bl + boff1 + kk);
            }
        }

        wmma::fragment<wmma::matrix_b, 16, 16, 16, __nv_bfloat16, wmma::col_major> fbh[3], fbl[3];
        for (int ni = 0; ni < 3; ni++) {
            wmma::load_matrix_sync(fbh[ni], &sBh[wn * 48 + ni * 16][0], RS);
            wmma::load_matrix_sync(fbl[ni], &sBl[wn * 48 + ni * 16][0], RS);
        }
        for (int mi = 0; mi < 4; mi++) {
            wmma::fragment<wmma::matrix_a, 16, 16, 16, __nv_bfloat16, wmma::row_major> fah, fal;
            wmma::load_matrix_sync(fah, &sAh[wm * 64 + mi * 16][0], RS);
            wmma::load_matrix_sync(fal, &sAl[wm * 64 + mi * 16][0], RS);
            for (int ni = 0; ni < 3; ni++) {
                wmma::mma_sync(acc[mi][ni], fah, fbh[ni], acc[mi][ni]);
                wmma::mma_sync(acc[mi][ni], fah, fbl[ni], acc[mi][ni]);
                wmma::mma_sync(acc[mi][ni], fal, fbh[ni], acc[mi][ni]);
            }
        }
    }

    for (int mi = 0; mi < 4; mi++) {
        for (int ni = 0; ni < 3; ni++) {
            size_t r = (size_t)(row0 + wm * 64 + mi * 16);
            size_t cc = (size_t)(cls * NPC + wn * 48 + ni * 16);
            wmma::store_matrix_sync(&g_CM[r * ROWW + cc], acc[mi][ni], ROWW, wmma::mem_row_major);
        }
    }
}

// ---------------- |X|^2 -> bark energies (+ internal noise), 8 frames/block ----------------
__global__ void k_bark() {
    int fb = blockIdx.x;
    int tid = threadIdx.x;
    __shared__ float P[8][768];
    for (int i = 0; i < 8; i++) {
        int fg = fb * 8 + i;
        const float* crow = &g_CM[(size_t)fg * ROWW];
        for (int j = tid; j < NBINS; j += 128) {
            int k = j + 3;
            int c = k % 9;
            int k0 = (c >= 3) ? c : c + 9;
            int p = (k - k0) / 9;
            float2 v = *(const float2*)&crow[c * NPC + 2 * p];
            P[i][j] = v.x * v.x + v.y * v.y;
        }
    }
    __syncthreads();
    if (tid < ZB) {
        float acc[8] = {0, 0, 0, 0, 0, 0, 0, 0};
        for (int j = 0; j < NBINS; j++) {
            float bv = g_BARK[j * 112 + tid];
            for (int i = 0; i < 8; i++) acc[i] += P[i][j] * bv;
        }
        float wn = g_WN[tid];
        for (int i = 0; i < 8; i++)
            g_UEP[(size_t)(fb * 8 + i) * 112 + tid] = fmaxf(acc[i], 1e-12f) + wn;
    }
}

// ---------------- frequency smearing (faithful to reference broadcasts) ----------------
__global__ void k_smear() {
    int fg = blockIdx.x;
    int tid = threadIdx.x;
    __shared__ float m2[ZB], Su[ZB], icol[ZB];
    if (tid < ZB) {
        float lg = log2f(g_UEP[(size_t)fg * 112 + tid]);
        float L = 3.0102999566f * lg;
        m2[tid] = fminf(0.30102999566f * lg, 30.0f);
        Su[tid] = g_SU0[tid] + 0.2f * L;
    }
    __syncthreads();
    if (tid < ZB) {
        int c = tid;
        float colsum = 0.f;
        for (int r = 0; r < ZB; r++) {
            float slope = (r <= c) ? 27.0f : Su[r];
            float e1 = 0.025f * (float)(r - c) * slope;
            float m = fminf(e1, 30.0f) + m2[r];
            colsum += exp2f(m * LOG2_10);
        }
        icol[c] = exp2f(-0.4f * log2f(colsum));
    }
    __syncthreads();
    if (tid < ZB) {
        int c = tid;
        float acc = 0.f;
        for (int r = 0; r < ZB; r++) {
            float slope = (r <= c) ? 27.0f : Su[r];
            float e1 = 0.025f * (float)(r - c) * slope;
            float m = fminf(e1, 30.0f) + m2[r];
            acc += exp2f(0.4f * LOG2_10 * m) * icol[r];
        }
        float E2 = exp2f(2.5f * log2f(acc)) * g_NORMI[c];
        int b = fg / NFRAMES, f = fg % NFRAMES;
        g_SM[((size_t)b * ZB + c) * NFRAMES + f] = E2;
    }
}

// ---------------- per-band IIR + max ----------------
__global__ void k_iir(float* __restrict__ out) {
    int idx = blockIdx.x * blockDim.x + threadIdx.x;
    if (idx >= NBATCH * ZB) return;
    int z = idx % ZB;
    float a = g_A[z], b0 = 1.f - a;
    const float* row = &g_SM[(size_t)idx * NFRAMES];
    float* orow = &out[(size_t)idx * NFRAMES];
    float ef = 0.f;
    for (int t = 0; t < NFRAMES; t++) {
        float u = row[t];
        float xin = (t == 0) ? 0.f : u;
        ef = fmaf(a, ef, b0 * xin);
        orow[t] = fmaxf(ef, u);
    }
}

// ---------------- launch ----------------
extern "C" void kernel_launch(void* const* d_in, const int* in_sizes, int n_in,
                              void* d_out, int out_size) {
    const float* pred = (const float*)d_in[0];
    const float* targ = (const float*)d_in[1];
    float* out = (float*)d_out;

    k_consts<<<1, 256>>>();
    k_barkmat<<<(NBINS * ZB + 255) / 256, 256>>>();
    k_facmag<<<dim3(KWIN, 10), 128>>>();
    k_facred<<<1, 320>>>();
    k_tw2<<<NCLS * NPC, 128>>>();
    k_fold<<<MTOT, 256>>>(pred, targ);
    k_gemm2<<<dim3(1, MPAD / 128, NCLS), 256>>>();
    k_bark<<<NFRAMES, 128>>>();
    k_smear<<<MTOT, 128>>>();
    k_iir<<<(NBATCH * ZB + 127) / 128, 128>>>(out);
}

// round 10
// speedup vs baseline: 1.6778x; 1.0550x over previous
#include <cuda_runtime.h>
#include <cuda_bf16.h>
#include <mma.h>
#include <math.h>

// ---------------- problem constants ----------------
#define NFFT    1881
#define STEPSZ  941
#define ZB      109
#define NFRAMES 468
#define NBATCH  8
#define MTOT    (NBATCH*NFRAMES)
#define MPAD    3840
#define NBINS   765
#define TLEN    441000
#define LOG2_10 3.321928094887362f
#define KLO     20
#define KHI     71
#define KWIN    (KHI-KLO)
#define RS      24
// CT factorization: 1881 = 9 x 209
#define N2CNT   209
#define KP2     432            // 2*209 = 418 padded to 432 (27 x 16)
#define NT2     (KP2/16)       // 27
#define NCLS    9
#define NPC     192            // per-class N: 85 bins x2 padded to 192
#define ROWW    (NCLS*NPC)     // 1728 floats per CM row
#define BM      64             // gemm M tile

// ---------------- scratch (static device memory; no allocations) ----------------
__device__ __align__(16) __nv_bfloat16 g_Ah[(size_t)NCLS * MPAD * KP2];
__device__ __align__(16) __nv_bfloat16 g_Al[(size_t)NCLS * MPAD * KP2];
__device__ __align__(16) __nv_bfloat16 g_Bh[NCLS * NPC * KP2];
__device__ __align__(16) __nv_bfloat16 g_Bl[NCLS * NPC * KP2];
__device__ __align__(16) float g_CM[(size_t)MPAD * ROWW];
__device__ __align__(16) float g_BARK[NBINS * 112];
__device__ __align__(16) float g_UEP[MTOT * 112];
__device__ __align__(16) float g_SM[NBATCH * ZB * NFRAMES];
__device__ __align__(16) float2 g_TRIG[NFFT];
__device__ __align__(16) float g_CALSW[10 * NFFT];
__device__ float g_ESC[NBINS];
__device__ float g_W[NFFT];
__device__ float g_FC[ZB], g_SU0[ZB], g_WN[ZB], g_A[ZB], g_NORMI[ZB];
__device__ float g_FMAG[10 * KWIN];
__device__ float g_FAC[1];

// ---------------- setup A: tables (grid-strided, multi-block) ----------------
__global__ void k_tab() {
    int gt = blockIdx.x * blockDim.x + threadIdx.x;
    int gs = gridDim.x * blockDim.x;
    for (int n = gt; n < NFFT; n += gs)
        g_W[n] = (float)(0.5 * (1.0 - cospi(2.0 * n / 1880.0)));
    for (int m = gt; m < NFFT; m += gs) {
        double ph = 2.0 * (double)m / 1881.0;
        g_TRIG[m] = make_float2((float)cospi(ph), (float)sinpi(ph));
    }
    for (int i = gt; i < 10 * NFFT; i += gs) {
        int fr = i / NFFT, n = i % NFFT;
        int t = fr * STEPSZ + n;
        int p = (t * 2039) % 88200;
        float sv = sinpif((float)p * (1.0f / 44100.0f));
        float wp = 0.5f * (1.0f - cospif((float)(2 * n) * (1.0f / 1881.0f)));
        g_CALSW[i] = wp * sv;
    }
    for (int j = gt; j < NBINS; j += gs) {
        int bin = j + 3;
        float f = 22050.0f * (float)bin / 941.0f;
        float fk = f * 0.001f;
        float lgfk = log2f(fk);
        float Wdb = -2.184f * exp2f(-0.8f * lgfk)
                  + 6.5f * expf(-0.6f * (fk - 3.3f) * (fk - 3.3f))
                  - 0.001f * exp2f(3.6f * lgfk);
        g_ESC[j] = exp2f(Wdb * (LOG2_10 / 20.f)) * (1.0f / 1881.0f);
    }
    if (gt < ZB) {
        double zL = 7.0 * asinh(80.0 / 650.0);
        double ze = zL + 0.25 * gt;
        double fcd = 650.0 * sinh((ze + 0.125) / 7.0);
        float fc = (float)fcd;
        g_FC[gt] = fc;
        g_SU0[gt] = -24.0f - 230.0f / fc;
        g_WN[gt] = (float)pow(10.0, 0.4 * 0.364 * pow(fcd / 1000.0, -0.8));
        double tau = 0.008 + 2.2 / fcd;
        g_A[gt] = (float)exp(-4.0 / (187.5 * tau));
    }
}

// ---------------- setup B: Ec-based norm_inv (needs SU0) ----------------
__global__ void k_norm() {
    int tid = threadIdx.x;
    __shared__ float srow[ZB];
    if (tid < ZB) {
        int r = tid; float s = 0.f;
        for (int c = 0; c < ZB; c++) {
            float slope = (r <= c) ? 27.0f : g_SU0[r];
            float e = fminf(0.025f * (float)(r - c) * slope, 30.0f);
            s += exp2f(e * LOG2_10);
        }
        srow[r] = s;
    }
    __syncthreads();
    if (tid < ZB) {
        int r = tid; float t = 0.f;
        for (int c = 0; c < ZB; c++) {
            float slope = (r <= c) ? 27.0f : g_SU0[r];
            float e = fminf(0.025f * (float)(r - c) * slope, 30.0f);
            float ec = exp2f(e * LOG2_10) / srow[c];
            t += exp2f(0.4f * log2f(ec));
        }
        g_NORMI[r] = exp2f(-2.5f * log2f(t));
    }
}

// ---------------- setup: bark overlap matrix (fp64, faithful) ----------------
__global__ void k_barkmat() {
    int idx = blockIdx.x * blockDim.x + threadIdx.x;
    if (idx >= NBINS * ZB) return;
    int k = idx / ZB, j = idx % ZB;
    double df = 44100.0 / 1881.0;
    int bin = k + 3;
    double blo = bin * df - df / 2.0, bhi = bin * df + df / 2.0;
    double zL = 7.0 * asinh(80.0 / 650.0);
    double felo = 650.0 * sinh((zL + 0.25 * j) / 7.0);
    double fehi = 650.0 * sinh((zL + 0.25 * (j + 1)) / 7.0);
    double ov = fmin(bhi, fehi) - fmax(blo, felo);
    ov = fmax(ov, 0.0) / df;
    g_BARK[k * 112 + j] = (float)ov;
}

// ---------------- setup: FAC calibration (peak near bin 43.5) ----------------
__global__ void k_facmag() {
    int k = blockIdx.x + KLO;
    int fr = blockIdx.y;
    int tid = threadIdx.x;
    const float* sw = &g_CALSW[fr * NFFT];
    float re = 0.f, im = 0.f;
    for (int n = tid; n < NFFT; n += 128) {
        int m = (k * n) % NFFT;
        float2 t = g_TRIG[m];
        float wx = sw[n];
        re += wx * t.x;
        im += wx * t.y;
    }
    __shared__ float sre[128], sim[128];
    sre[tid] = re; sim[tid] = im; __syncthreads();
    for (int o = 64; o > 0; o >>= 1) {
        if (tid < o) { sre[tid] += sre[tid + o]; sim[tid] += sim[tid + o]; }
        __syncthreads();
    }
    if (tid == 0) g_FMAG[fr * KWIN + blockIdx.x] = sqrtf(sre[0] * sre[0] + sim[0] * sim[0]);
}

__global__ void k_facred() {
    int w = threadIdx.x >> 5, lane = threadIdx.x & 31;
    __shared__ float fmx[10];
    if (w < 10) {
        float mx = 0.f;
        for (int k = lane; k < KWIN; k += 32) mx = fmaxf(mx, g_FMAG[w * KWIN + k]);
        for (int o = 16; o > 0; o >>= 1) mx = fmaxf(mx, __shfl_xor_sync(0xffffffff, mx, o));
        if (lane == 0) fmx[w] = mx;
    }
    __syncthreads();
    if (threadIdx.x == 0) {
        float total = 0.f;
        for (int fr = 0; fr < 10; fr++) total += fmx[fr];
        g_FAC[0] = exp2f(4.6f * LOG2_10) / (total * 0.1f);
    }
}

// ---------------- setup: per-class twiddle matrices B (split bf16 hi/lo) ----------------
__global__ void k_tw2() {
    int gid = blockIdx.x;           // 0 .. 9*192-1
    int c = gid / NPC, col = gid - c * NPC;
    float fac = g_FAC[0];
    int p = col >> 1;
    int k0 = (c >= 3) ? c : c + 9;
    int k = k0 + 9 * p;
    bool valid = (p < 85);
    float sc = valid ? fac * g_ESC[k - 3] : 0.f;
    for (int q = threadIdx.x; q < KP2; q += 128) {
        float v = 0.f;
        if (valid && q < 2 * N2CNT) {
            int n2 = q >> 1;
            float2 t = g_TRIG[(k * n2) % NFFT];
            if ((col & 1) == 0) v = (q & 1) ? t.y : t.x;
            else                v = (q & 1) ? t.x : -t.y;
            v *= sc;
        }
        __nv_bfloat16 h = __float2bfloat16(v);
        float r = v - __bfloat162float(h);
        size_t o = ((size_t)c * NPC + col) * KP2 + q;
        g_Bh[o] = h;
        g_Bl[o] = __float2bfloat16(r);
    }
}

// ---------------- stage 1: window + 9-point fold -> A (split bf16 hi/lo) ----------------
__global__ void k_fold(const float* __restrict__ pred, const float* __restrict__ targ) {
    __shared__ float xw[NFFT];
    int fg = blockIdx.x;
    int tid = threadIdx.x;          // 256
    int b = fg / NFRAMES, f = fg % NFRAMES;
    const float* src = (b < 4) ? pred + (size_t)b * TLEN : targ + (size_t)(b - 4) * TLEN;
    int start = f * STEPSZ;
    for (int n = tid; n < NFFT; n += 256) {
        int s = start + n;
        xw[n] = ((s < TLEN) ? src[s] : 0.f) * g_W[n];
    }
    __syncthreads();
    for (int idx = tid; idx < NFFT; idx += 256) {
        int c = idx / N2CNT;
        int n2 = idx - c * N2CNT;
        float yr = 0.f, yi = 0.f;
        for (int n1 = 0; n1 < 9; n1++) {
            int m = ((c * n1) % 9) * N2CNT;
            float2 t = g_TRIG[m];
            float xv = xw[n2 + N2CNT * n1];
            yr = fmaf(xv, t.x, yr);
            yi = fmaf(-xv, t.y, yi);
        }
        size_t base = ((size_t)c * MPAD + fg) * KP2 + 2 * n2;
        __nv_bfloat16 hr = __float2bfloat16(yr);
        __nv_bfloat16 hiq = __float2bfloat16(yi);
        g_Ah[base] = hr;
        g_Ah[base + 1] = hiq;
        g_Al[base] = __float2bfloat16(yr - __bfloat162float(hr));
        g_Al[base + 1] = __float2bfloat16(yi - __bfloat162float(hiq));
    }
    if (tid < KP2 - 2 * N2CNT) {
        __nv_bfloat16 z = __float2bfloat16(0.f);
        for (int c = 0; c < NCLS; c++) {
            size_t base = ((size_t)c * MPAD + fg) * KP2 + 2 * N2CNT + tid;
            g_Ah[base] = z;
            g_Al[base] = z;
        }
    }
}

// ---------------- stage 2: split-bf16 tensor GEMM per class ----------------
// block 64M x 192N, 8 warps = 2m x 4n, warp tile 32x48 (acc 48 regs -> 2 blocks/SM)
__global__ __launch_bounds__(256, 2) void k_gemm2() {
    using namespace nvcuda;
    __shared__ __align__(16) __nv_bfloat16 sAh[BM][RS];
    __shared__ __align__(16) __nv_bfloat16 sAl[BM][RS];
    __shared__ __align__(16) __nv_bfloat16 sBh[NPC][RS];
    __shared__ __align__(16) __nv_bfloat16 sBl[NPC][RS];

    const int tid = threadIdx.x;
    const int w = tid >> 5;
    const int wm = w & 1;           // 2 warp-rows -> 32 M each
    const int wn = w >> 1;          // 4 warp-cols -> 48 N each
    const int cls = blockIdx.z;
    const int row0 = blockIdx.y * BM;

    const bool hasA = (tid < 128);
    const int lrA = tid >> 1;            // A rows 0..63 (tid<128)
    const int lh = (tid & 1) * 8;
    const size_t aoff = ((size_t)cls * MPAD + row0 + (hasA ? lrA : 0)) * KP2 + lh;
    const int lrB0 = tid >> 1;           // B rows 0..127 (all threads)
    const size_t boff0 = ((size_t)cls * NPC + lrB0) * KP2 + lh;
    const int lrB1 = 128 + (tid >> 1);   // B rows 128..191 (tid<128)
    const size_t boff1 = ((size_t)cls * NPC + (hasA ? lrB1 : 128)) * KP2 + lh;

    uint4 rah = make_uint4(0, 0, 0, 0), ral = rah, rbh1 = rah, rbl1 = rah;
    if (hasA) {
        rah = *(const uint4*)(g_Ah + aoff);
        ral = *(const uint4*)(g_Al + aoff);
        rbh1 = *(const uint4*)(g_Bh + boff1);
        rbl1 = *(const uint4*)(g_Bl + boff1);
    }
    uint4 rbh0 = *(const uint4*)(g_Bh + boff0);
    uint4 rbl0 = *(const uint4*)(g_Bl + boff0);

    wmma::fragment<wmma::accumulator, 16, 16, 16, float> acc[2][3];
    for (int i = 0; i < 2; i++) {
        for (int j = 0; j < 3; j++) wmma::fill_fragment(acc[i][j], 0.f);
    }

    for (int kt = 0; kt < NT2; kt++) {
        __syncthreads();
        if (hasA) {
            *(uint4*)(&sAh[lrA][lh]) = rah;
            *(uint4*)(&sAl[lrA][lh]) = ral;
            *(uint4*)(&sBh[lrB1][lh]) = rbh1;
            *(uint4*)(&sBl[lrB1][lh]) = rbl1;
        }
        *(uint4*)(&sBh[lrB0][lh]) = rbh0;
        *(uint4*)(&sBl[lrB0][lh]) = rbl0;
        __syncthreads();
        if (kt + 1 < NT2) {
            size_t kk = (size_t)(kt + 1) * 16;
            if (hasA) {
                rah = *(const uint4*)(g_Ah + aoff + kk);
                ral = *(const uint4*)(g_Al + aoff + kk);
                rbh1 = *(const uint4*)(g_Bh + boff1 + kk);
                rbl1 = *(const uint4*)(g_Bl + boff1 + kk);
            }
            rbh0 = *(const uint4*)(g_Bh + boff0 + kk);
            rbl0 = *(const uint4*)(g_Bl + boff0 + kk);
        }

        wmma::fragment<wmma::matrix_b, 16, 16, 16, __nv_bfloat16, wmma::col_major> fbh[3], fbl[3];
        for (int ni = 0; ni < 3; ni++) {
            wmma::load_matrix_sync(fbh[ni], &sBh[wn * 48 + ni * 16][0], RS);
            wmma::load_matrix_sync(fbl[ni], &sBl[wn * 48 + ni * 16][0], RS);
        }
        for (int mi = 0; mi < 2; mi++) {
            wmma::fragment<wmma::matrix_a, 16, 16, 16, __nv_bfloat16, wmma::row_major> fah, fal;
            wmma::load_matrix_sync(fah, &sAh[wm * 32 + mi * 16][0], RS);
            wmma::load_matrix_sync(fal, &sAl[wm * 32 + mi * 16][0], RS);
            for (int ni = 0; ni < 3; ni++) {
                wmma::mma_sync(acc[mi][ni], fah, fbh[ni], acc[mi][ni]);
                wmma::mma_sync(acc[mi][ni], fah, fbl[ni], acc[mi][ni]);
                wmma::mma_sync(acc[mi][ni], fal, fbh[ni], acc[mi][ni]);
            }
        }
    }

    for (int mi = 0; mi < 2; mi++) {
        for (int ni = 0; ni < 3; ni++) {
            size_t r = (size_t)(row0 + wm * 32 + mi * 16);
            size_t cc = (size_t)(cls * NPC + wn * 48 + ni * 16);
            wmma::store_matrix_sync(&g_CM[r * ROWW + cc], acc[mi][ni], ROWW, wmma::mem_row_major);
        }
    }
}

// ---------------- |X|^2 -> bark energies (+ internal noise), 8 frames/block ----------------
__global__ void k_bark() {
    int fb = blockIdx.x;
    int tid = threadIdx.x;
    __shared__ float P[8][768];
    for (int i = 0; i < 8; i++) {
        int fg = fb * 8 + i;
        const float* crow = &g_CM[(size_t)fg * ROWW];
        for (int j = tid; j < NBINS; j += 128) {
            int k = j + 3;
            int c = k % 9;
            int k0 = (c >= 3) ? c : c + 9;
            int p = (k - k0) / 9;
            float2 v = *(const float2*)&crow[c * NPC + 2 * p];
            P[i][j] = v.x * v.x + v.y * v.y;
        }
    }
    __syncthreads();
    if (tid < ZB) {
        float acc[8] = {0, 0, 0, 0, 0, 0, 0, 0};
        for (int j = 0; j < NBINS; j++) {
            float bv = g_BARK[j * 112 + tid];
            for (int i = 0; i < 8; i++) acc[i] += P[i][j] * bv;
        }
        float wn = g_WN[tid];
        for (int i = 0; i < 8; i++)
            g_UEP[(size_t)(fb * 8 + i) * 112 + tid] = fmaxf(acc[i], 1e-12f) + wn;
    }
}

// ---------------- frequency smearing (faithful to reference broadcasts) ----------------
__global__ void k_smear() {
    int fg = blockIdx.x;
    int tid = threadIdx.x;
    __shared__ float m2[ZB], Su[ZB], icol[ZB];
    if (tid < ZB) {
        float lg = log2f(g_UEP[(size_t)fg * 112 + tid]);
        float L = 3.0102999566f * lg;
        m2[tid] = fminf(0.30102999566f * lg, 30.0f);
        Su[tid] = g_SU0[tid] + 0.2f * L;
    }
    __syncthreads();
    if (tid < ZB) {
        int c = tid;
        float colsum = 0.f;
        for (int r = 0; r < ZB; r++) {
            float slope = (r <= c) ? 27.0f : Su[r];
            float e1 = 0.025f * (float)(r - c) * slope;
            float m = fminf(e1, 30.0f) + m2[r];
            colsum += exp2f(m * LOG2_10);
        }
        icol[c] = exp2f(-0.4f * log2f(colsum));
    }
    __syncthreads();
    if (tid < ZB) {
        int c = tid;
        float acc = 0.f;
        for (int r = 0; r < ZB; r++) {
            float slope = (r <= c) ? 27.0f : Su[r];
            float e1 = 0.025f * (float)(r - c) * slope;
            float m = fminf(e1, 30.0f) + m2[r];
            acc += exp2f(0.4f * LOG2_10 * m) * icol[r];
        }
        float E2 = exp2f(2.5f * log2f(acc)) * g_NORMI[c];
        int b = fg / NFRAMES, f = fg % NFRAMES;
        g_SM[((size_t)b * ZB + c) * NFRAMES + f] = E2;
    }
}

// ---------------- per-band IIR + max ----------------
__global__ void k_iir(float* __restrict__ out) {
    int idx = blockIdx.x * blockDim.x + threadIdx.x;
    if (idx >= NBATCH * ZB) return;
    int z = idx % ZB;
    float a = g_A[z], b0 = 1.f - a;
    const float* row = &g_SM[(size_t)idx * NFRAMES];
    float* orow = &out[(size_t)idx * NFRAMES];
    float ef = 0.f;
    for (int t = 0; t < NFRAMES; t++) {
        float u = row[t];
        float xin = (t == 0) ? 0.f : u;
        ef = fmaf(a, ef, b0 * xin);
        orow[t] = fmaxf(ef, u);
    }
}

// ---------------- launch ----------------
extern "C" void kernel_launch(void* const* d_in, const int* in_sizes, int n_in,
                              void* d_out, int out_size) {
    const float* pred = (const float*)d_in[0];
    const float* targ = (const float*)d_in[1];
    float* out = (float*)d_out;

    k_tab<<<64, 256>>>();
    k_facmag<<<dim3(KWIN, 10), 128>>>();
    k_facred<<<1, 320>>>();
    k_tw2<<<NCLS * NPC, 128>>>();
    k_fold<<<MTOT, 256>>>(pred, targ);
    k_gemm2<<<dim3(1, MPAD / BM, NCLS), 256>>>();
    k_norm<<<1, 128>>>();
    k_barkmat<<<(NBINS * ZB + 255) / 256, 256>>>();
    k_bark<<<NFRAMES, 128>>>();
    k_smear<<<MTOT, 128>>>();
    k_iir<<<(NBATCH * ZB + 127) / 128, 128>>>(out);
}